// round 6
// baseline (speedup 1.0000x reference)
#include <cuda_runtime.h>

// Problem constants (B=8192, L=2048, T=1024)
#define NB 8192
#define NT 1024
#define THREADS 256            // 8 warps per block, 1 warp per row
#define ROWS_PER_BLOCK 8
#define NBLOCKS (NB / ROWS_PER_BLOCK)   // 1024

__device__ double g_sum = 0.0;          // zeroed by last warp each launch
__device__ unsigned int g_count = 0;    // zeroed by last warp each launch

struct Seg {
    float4 a, a2, c, c2;       // pred chunks
    float4 txA, txB, tyA, tyB; // targets
};

__device__ __forceinline__ void load_seg(
    Seg& s, int i, int lane,
    const float4* __restrict__ pv,
    const float4* __restrict__ txv,
    const float4* __restrict__ tyv)
{
    s.a   = pv[128 * i + 2 * lane];
    s.a2  = pv[128 * i + 2 * lane + 1];
    s.c   = pv[128 * i + 64 + 2 * lane];
    s.c2  = pv[128 * i + 64 + 2 * lane + 1];
    s.txA = txv[64 * i + lane];
    s.txB = txv[64 * i + 32 + lane];
    s.tyA = tyv[64 * i + lane];
    s.tyB = tyv[64 * i + 32 + lane];
}

// One warp owns one row; 4 segments of 256 points, software-pipelined.
// No shared memory, no block barriers.
__global__ __launch_bounds__(THREADS) void traj_loss_warp(
    const float* __restrict__ pred,
    const float* __restrict__ pos_true,
    float* __restrict__ out)
{
    const int lane = threadIdx.x & 31;
    const int warp = threadIdx.x >> 5;
    const int b    = blockIdx.x * ROWS_PER_BLOCK + warp;

    const float4* pv  = (const float4*)(pred + (size_t)b * (2 * NT));
    const float4* txv = (const float4*)(pos_true + (size_t)b * (2 * NT));
    const float4* tyv = (const float4*)(pos_true + (size_t)b * (2 * NT) + NT);

    float runx = 0.0f, runy = 0.0f;
    double esum = 0.0;

    Seg cur, nxt;
    load_seg(cur, 0, lane, pv, txv, tyv);

    #pragma unroll
    for (int i = 0; i < 4; i++) {
        if (i < 3) load_seg(nxt, i + 1, lane, pv, txv, tyv);  // prefetch next segment

        // per-chunk delta sums
        float Ax = cur.a.x + cur.a.z + cur.a2.x + cur.a2.z;
        float Ay = cur.a.y + cur.a.w + cur.a2.y + cur.a2.w;
        float Bx = cur.c.x + cur.c.z + cur.c2.x + cur.c2.z;
        float By = cur.c.y + cur.c.w + cur.c2.y + cur.c2.w;

        // 4-value warp inclusive scan
        float sAx = Ax, sAy = Ay, sBx = Bx, sBy = By;
        #pragma unroll
        for (int d = 1; d < 32; d <<= 1) {
            float u0 = __shfl_up_sync(0xffffffffu, sAx, d);
            float u1 = __shfl_up_sync(0xffffffffu, sAy, d);
            float u2 = __shfl_up_sync(0xffffffffu, sBx, d);
            float u3 = __shfl_up_sync(0xffffffffu, sBy, d);
            if (lane >= d) { sAx += u0; sAy += u1; sBx += u2; sBy += u3; }
        }
        float totAx = __shfl_sync(0xffffffffu, sAx, 31);
        float totAy = __shfl_sync(0xffffffffu, sAy, 31);
        float totBx = __shfl_sync(0xffffffffu, sBx, 31);
        float totBy = __shfl_sync(0xffffffffu, sBy, 31);

        // exclusive offsets + running carry
        float oAx = runx + sAx - Ax,         oAy = runy + sAy - Ay;
        float oBx = runx + totAx + sBx - Bx, oBy = runy + totAy + sBy - By;
        runx += totAx + totBx;
        runy += totAy + totBy;

        // cumsum + squared error
        float err = 0.0f, cx, cy, ex, ey;
        cx = oAx + cur.a.x;  cy = oAy + cur.a.y;  ex = cx - cur.txA.x; ey = cy - cur.tyA.x; err += ex * ex + ey * ey;
        cx += cur.a.z;       cy += cur.a.w;       ex = cx - cur.txA.y; ey = cy - cur.tyA.y; err += ex * ex + ey * ey;
        cx += cur.a2.x;      cy += cur.a2.y;      ex = cx - cur.txA.z; ey = cy - cur.tyA.z; err += ex * ex + ey * ey;
        cx += cur.a2.z;      cy += cur.a2.w;      ex = cx - cur.txA.w; ey = cy - cur.tyA.w; err += ex * ex + ey * ey;

        cx = oBx + cur.c.x;  cy = oBy + cur.c.y;  ex = cx - cur.txB.x; ey = cy - cur.tyB.x; err += ex * ex + ey * ey;
        cx += cur.c.z;       cy += cur.c.w;       ex = cx - cur.txB.y; ey = cy - cur.tyB.y; err += ex * ex + ey * ey;
        cx += cur.c2.x;      cy += cur.c2.y;      ex = cx - cur.txB.z; ey = cy - cur.tyB.z; err += ex * ex + ey * ey;
        cx += cur.c2.z;      cy += cur.c2.w;      ex = cx - cur.txB.w; ey = cy - cur.tyB.w; err += ex * ex + ey * ey;

        esum += (double)err;
        cur = nxt;
    }

    // warp reduce (double)
    #pragma unroll
    for (int d = 16; d > 0; d >>= 1)
        esum += __shfl_down_sync(0xffffffffu, esum, d);

    if (lane == 0) {
        atomicAdd(&g_sum, esum);
        __threadfence();
        unsigned int old = atomicAdd(&g_count, 1u);
        if (old == NB - 1) {
            // last warp: read-and-zero accumulator, reset counter (graph-replay safe)
            unsigned long long bits = atomicExch((unsigned long long*)&g_sum, 0ULL);
            g_count = 0;
            out[0] = (float)__longlong_as_double(bits);
        }
    }
}

extern "C" void kernel_launch(void* const* d_in, const int* in_sizes, int n_in,
                              void* d_out, int out_size)
{
    const float* pred     = (const float*)d_in[0];  // traj_pred
    // d_in[1] = traj_du_true — unused by the reference; never read.
    const float* pos_true = (const float*)d_in[2];  // traj_pos_true

    traj_loss_warp<<<NBLOCKS, THREADS>>>(pred, pos_true, (float*)d_out);
}

// round 7
// speedup vs baseline: 1.5162x; 1.5162x over previous
#include <cuda_runtime.h>

// Problem constants (B=8192, L=2048, T=1024)
#define NB 8192
#define NT 1024
#define THREADS 256
#define NWARPS (THREADS / 32)

__device__ double g_sum = 0.0;          // zeroed by last block each launch
__device__ unsigned int g_count = 0;    // zeroed by last block each launch

// Block-per-row. Thread t owns points 4t..4t+3 (8 contiguous pred floats).
// Error partials (e2, e1x, e1y) are computed relative to the thread's own
// chunk start, so they don't depend on the prefix scan; the global offset is
// folded in afterwards with 6 FMAs:  err = e2 + 2*O.e1 + 4*|O|^2.
__global__ __launch_bounds__(THREADS) void traj_loss_fused(
    const float* __restrict__ pred,
    const float* __restrict__ pos_true,
    float* __restrict__ out)
{
    const int b    = blockIdx.x;
    const int tid  = threadIdx.x;
    const int lane = tid & 31;
    const int warp = tid >> 5;

    // --- loads: all four issued up-front, independent (MLP) ---
    const float4* pv = (const float4*)(pred + (size_t)b * (2 * NT));
    float4 a = pv[2 * tid];       // x0 y0 x1 y1
    float4 c = pv[2 * tid + 1];   // x2 y2 x3 y3

    const float* tp = pos_true + (size_t)b * (2 * NT);
    float4 tx = ((const float4*)tp)[tid];        // unit-stride
    float4 ty = ((const float4*)(tp + NT))[tid]; // unit-stride

    // --- thread-local prefix positions (relative to own chunk start) ---
    float p1x = a.x,       p1y = a.y;
    float p2x = p1x + a.z, p2y = p1y + a.w;
    float p3x = p2x + c.x, p3y = p2y + c.y;
    float p4x = p3x + c.z, p4y = p3y + c.w;   // == thread delta totals (lx, ly)

    // --- error partials, independent of the scan ---
    float dx, dy;
    float e2 = 0.0f, e1x = 0.0f, e1y = 0.0f;
    dx = p1x - tx.x; dy = p1y - ty.x; e2 += dx * dx + dy * dy; e1x += dx; e1y += dy;
    dx = p2x - tx.y; dy = p2y - ty.y; e2 += dx * dx + dy * dy; e1x += dx; e1y += dy;
    dx = p3x - tx.z; dy = p3y - ty.z; e2 += dx * dx + dy * dy; e1x += dx; e1y += dy;
    dx = p4x - tx.w; dy = p4y - ty.w; e2 += dx * dx + dy * dy; e1x += dx; e1y += dy;

    // --- warp inclusive scan of thread delta totals (runs concurrently with
    //     the FMA chain above from the scheduler's perspective) ---
    const float lx = p4x, ly = p4y;
    float sx = lx, sy = ly;
    #pragma unroll
    for (int d = 1; d < 32; d <<= 1) {
        float ux = __shfl_up_sync(0xffffffffu, sx, d);
        float uy = __shfl_up_sync(0xffffffffu, sy, d);
        if (lane >= d) { sx += ux; sy += uy; }
    }

    __shared__ float wx[NWARPS], wy[NWARPS];
    if (lane == 31) { wx[warp] = sx; wy[warp] = sy; }
    __syncthreads();

    // exclusive offset for this thread = (inclusive - local) + prior warp totals
    float ox = sx - lx, oy = sy - ly;
    #pragma unroll
    for (int w = 0; w < NWARPS - 1; w++) {
        float addx = wx[w], addy = wy[w];
        if (w < warp) { ox += addx; oy += addy; }
    }

    // --- fold offset into error: 6 FMAs ---
    float err = e2 + 2.0f * (ox * e1x + oy * e1y) + 4.0f * (ox * ox + oy * oy);

    // --- block reduce: float shuffles, double only at block partial ---
    #pragma unroll
    for (int d = 16; d > 0; d >>= 1)
        err += __shfl_down_sync(0xffffffffu, err, d);

    __shared__ float wsum[NWARPS];
    if (lane == 0) wsum[warp] = err;
    __syncthreads();

    if (warp == 0 && lane == 0) {
        double v = 0.0;
        #pragma unroll
        for (int w = 0; w < NWARPS; w++) v += (double)wsum[w];

        atomicAdd(&g_sum, v);
        __threadfence();
        unsigned int old = atomicAdd(&g_count, 1u);
        if (old == NB - 1) {
            // last block: read-and-zero accumulator, reset counter (graph-replay safe)
            unsigned long long bits = atomicExch((unsigned long long*)&g_sum, 0ULL);
            g_count = 0;
            out[0] = (float)__longlong_as_double(bits);
        }
    }
}

extern "C" void kernel_launch(void* const* d_in, const int* in_sizes, int n_in,
                              void* d_out, int out_size)
{
    const float* pred     = (const float*)d_in[0];  // traj_pred
    // d_in[1] = traj_du_true — unused by the reference; never read.
    const float* pos_true = (const float*)d_in[2];  // traj_pos_true

    traj_loss_fused<<<NB, THREADS>>>(pred, pos_true, (float*)d_out);
}